// round 8
// baseline (speedup 1.0000x reference)
#include <cuda_runtime.h>
#include <math.h>

// Problem constants (static shapes from reference)
#define NN   2048      // nodes
#define NE   8192      // edges (E)
#define KK   1024      // K_KEEP
#define MNE  16384     // node-graph edges
#define MEE  65536     // edge-graph edges
#define CC   256       // feature dim (CN == CE)
#define LANM 48        // Lanczos iterations (R5 value, rel_err 6.8e-5)

// Output layout (float offsets, concatenated flattened outputs in tuple order)
#define OFF_XN   0u         // x_n_out   [1024,256]
#define OFF_L0   262144u    // L0s       [1024,1024]
#define OFF_XE   1310720u   // x_e_out   [8192,256]
#define OFF_L1   3407872u   // L1s       [8192,8192]
#define OFF_PAR  70516736u  // par_masked[1024,8192]
#define OFF_XN0  78905344u  // x_n0_out  [1024,256]
#define OFF_XE0  79167488u  // x_e0_out  [8192,256]

// ---- distributed zero plan: chunks of 512 float4 (8 KB) -------------------
// Z-space = region B (L1s+PAR contiguous, 36864 chunks) then L0 (512 chunks).
#define A_BASE_F4  (OFF_L0 / 4u)     // 65536
#define B_BASE_F4  (OFF_L1 / 4u)     // 851968
#define B_CHUNKS   36864u
#define TOT_CHUNKS 37376u
// per-kernel chunk ranges [c0, c1)
#define ZR_ROWS_0  0u
#define ZR_ROWS_1  6200u
#define ZR_SCAT_1  12400u
#define ZR_SCOR_1  18600u
#define ZR_RANK_1  24800u
#define ZR_TOPO_1  31000u
#define ZR_MEGA_1  TOT_CHUNKS

#define ZGRID 592

// ---------------- scratch (device globals) ----------------------------------
__device__ float d_t_n[NN], d_u_n[NN], d_t_e[NE], d_u_e[NE];
__device__ float d_g_n[NN], d_g_e[NE];
__device__ float d_score_n[NN], d_score_e[NE], d_joint[NN];
__device__ int   d_mask[NN], d_idx_keep[KK];
__device__ float d_keep_f[NE];
__device__ int   d_kept_rs[NE], d_kept_rd[NE];
__device__ int   d_rowptr[KK + 1];
__device__ int   d_adj_node[2 * NE], d_adj_edge[2 * NE];
__device__ float d_adj_sign[2 * NE];
__device__ float d_scale;        // 2 / lambda_max(L0)
__device__ unsigned d_tick[8];   // per-kernel zero tickets (reset by k_sparse)

// ---------------- warp-ticket zero filler ------------------------------------
__device__ __forceinline__ void zero_tickets(float4* o4, int slot,
                                             unsigned c0, unsigned c1) {
    const float4 z4 = make_float4(0.f, 0.f, 0.f, 0.f);
    int lane = threadIdx.x & 31;
    for (;;) {
        unsigned t;
        if (lane == 0) t = atomicAdd(&d_tick[slot], 1u);
        t = __shfl_sync(0xffffffffu, t, 0);
        unsigned c = c0 + t;
        if (c >= c1) break;
        unsigned base = (c < B_CHUNKS) ? (B_BASE_F4 + c * 512u)
                                       : (A_BASE_F4 + (c - B_CHUNKS) * 512u);
#pragma unroll
        for (int k = 0; k < 16; k++)
            o4[base + (unsigned)k * 32u + lane] = z4;
    }
}

// ---------------- K1: row projections (+ scratch zero) + zero filler ---------
__global__ void __launch_bounds__(1024) k_rows(
    float* __restrict__ out,
    const float* __restrict__ x_n, const float* __restrict__ x_e,
    const float* __restrict__ Wn0, const float* __restrict__ Wn1,
    const float* __restrict__ We0, const float* __restrict__ We1) {
    int bid = blockIdx.x, tid = threadIdx.x;
    if (bid < 80) {
        int gt = bid * 1024 + tid;
        if (gt < NN + NE) {                 // zero per-launch accumulators
            if (gt < NN) { d_g_n[gt] = 0.f; d_joint[gt] = 0.f; }
            else d_g_e[gt - NN] = 0.f;
        }
        int w = bid * 32 + (tid >> 5);      // 2560 warps, 4 rows each
        int lane = tid & 31;
#pragma unroll
        for (int i = 0; i < 4; i++) {
            int row = w + i * 2560;
            const float *x, *W0, *W1;
            if (row < NN) { x = x_n + (size_t)row * CC;        W0 = Wn0; W1 = Wn1; }
            else          { x = x_e + (size_t)(row - NN) * CC; W0 = We0; W1 = We1; }
            float u = 0.f, t = 0.f;
#pragma unroll
            for (int k = lane; k < CC; k += 32) {
                float xv = x[k];
                float w1 = W1[k];
                t = fmaf(xv, w1, t);
                u = fmaf(xv, W0[k] + w1, u);
            }
#pragma unroll
            for (int o = 16; o; o >>= 1) {
                u += __shfl_down_sync(0xffffffffu, u, o);
                t += __shfl_down_sync(0xffffffffu, t, o);
            }
            if (lane == 0) {
                if (row < NN) { d_u_n[row] = u; d_t_n[row] = t; }
                else          { d_u_e[row - NN] = u; d_t_e[row - NN] = t; }
            }
        }
    }
    zero_tickets((float4*)out, 0, ZR_ROWS_0, ZR_ROWS_1);
}

// ---------------- K2: scatter weighted scalar aggregates + zero filler -------
__global__ void __launch_bounds__(1024) k_scatter_g(
    float* __restrict__ out,
    const int* __restrict__ ein, const float* __restrict__ ewn,
    const int* __restrict__ eie, const float* __restrict__ ewe) {
    int bid = blockIdx.x, tid = threadIdx.x;
    if (bid < 80) {
        int i = bid * 1024 + tid;           // exactly MNE+MEE = 81920
        if (i < MNE) {
            int s = ein[i], d = ein[MNE + i];
            atomicAdd(&d_g_n[d], ewn[i] * d_t_n[s]);
        } else {
            int j = i - MNE;
            int s = eie[j], d = eie[MEE + j];
            atomicAdd(&d_g_e[d], ewe[j] * d_t_e[s]);
        }
    }
    zero_tickets((float4*)out, 1, ZR_ROWS_1, ZR_SCAT_1);
}

// ---------------- K3: sigmoid scores + joint accumulation + zero filler ------
__global__ void __launch_bounds__(1024) k_scores_joint(
    float* __restrict__ out,
    const float* __restrict__ bn, const float* __restrict__ be,
    const int* __restrict__ ei) {
    int bid = blockIdx.x, tid = threadIdx.x;
    if (bid < 10) {
        int i = bid * 1024 + tid;           // exactly NN+NE = 10240
        if (i < NN) {
            float z = d_u_n[i] - d_g_n[i] + bn[0];
            float s = 1.f / (1.f + expf(-z));
            d_score_n[i] = s;
            atomicAdd(&d_joint[i], s);
        } else {
            int j = i - NN;
            float z = d_u_e[j] - d_g_e[j] + be[0];
            float s = 1.f / (1.f + expf(-z));
            d_score_e[j] = s;
            float c = 0.125f * s;
            atomicAdd(&d_joint[ei[j]], c);
            atomicAdd(&d_joint[ei[NE + j]], c);
        }
    }
    zero_tickets((float4*)out, 2, ZR_SCAT_1, ZR_SCOR_1);
}

// ---------------- K4: exact top-K rank counting + zero filler ----------------
__global__ void __launch_bounds__(1024) k_rank(float* __restrict__ out) {
    int bid = blockIdx.x, tid = threadIdx.x;
    if (bid < 64) {
        int w = bid * 32 + (tid >> 5);      // 2048 warps, one node each
        int lane = tid & 31;
        float vi = d_joint[w];
        int cnt = 0;
        for (int j = lane; j < NN; j += 32) {
            float vj = d_joint[j];
            cnt += (vj > vi) || (vj == vi && j < w);
        }
#pragma unroll
        for (int o = 16; o; o >>= 1) cnt += __shfl_down_sync(0xffffffffu, cnt, o);
        if (lane == 0) d_mask[w] = (cnt < KK) ? 1 : 0;
    }
    zero_tickets((float4*)out, 3, ZR_SCOR_1, ZR_RANK_1);
}

// ---------------- block exclusive scan helper (1024 threads) ----------------
__device__ __forceinline__ int exclScan1024(int v, int* tmp) {
    int lane = threadIdx.x & 31, w = threadIdx.x >> 5;
    int incl = v;
#pragma unroll
    for (int o = 1; o < 32; o <<= 1) {
        int n = __shfl_up_sync(0xffffffffu, incl, o);
        if (lane >= o) incl += n;
    }
    if (lane == 31) tmp[w] = incl;
    __syncthreads();
    if (w == 0) {
        int x = tmp[lane];
#pragma unroll
        for (int o = 1; o < 32; o <<= 1) {
            int n = __shfl_up_sync(0xffffffffu, x, o);
            if (lane >= o) x += n;
        }
        tmp[lane] = x;
    }
    __syncthreads();
    int off = w ? tmp[w - 1] : 0;
    return off + incl - v;
}

// ---------------- K5: topology (block 0) + zero filler ------------------------
__global__ void __launch_bounds__(1024) k_topo(float* __restrict__ out,
                                               const int* __restrict__ ei) {
    int tid = threadIdx.x;
    if (blockIdx.x == 0) {
        __shared__ int s_row[NN];
        __shared__ int s_deg[KK];
        __shared__ int s_cur[KK];
        __shared__ int tmp[32];
        // Phase A: compact kept nodes -> idx_keep (ascending), row map
        int m0 = d_mask[2 * tid], m1 = d_mask[2 * tid + 1];
        int ex = exclScan1024(m0 + m1, tmp);
        if (m0) { s_row[2 * tid] = ex; d_idx_keep[ex] = 2 * tid; }
        else    s_row[2 * tid] = -1;
        int ex1 = ex + m0;
        if (m1) { s_row[2 * tid + 1] = ex1; d_idx_keep[ex1] = 2 * tid + 1; }
        else    s_row[2 * tid + 1] = -1;
        s_deg[tid] = 0;
        s_cur[tid] = 0;
        __syncthreads();
        // Phase B: keep_e + endpoint rows + degree count
        for (int e = tid; e < NE; e += 1024) {
            int s = ei[e], d = ei[NE + e];
            int rs = s_row[s], rd = s_row[d];
            int keep = (rs >= 0) && (rd >= 0);
            d_keep_f[e] = keep ? 1.f : 0.f;
            if (keep && s != d) {
                d_kept_rs[e] = rs;
                d_kept_rd[e] = rd;
                atomicAdd(&s_deg[rs], 1);
                atomicAdd(&s_deg[rd], 1);
            } else {
                d_kept_rs[e] = -1;
            }
        }
        __syncthreads();
        // Phase C: row pointers
        int v = s_deg[tid];
        int rp = exclScan1024(v, tmp);
        d_rowptr[tid] = rp;
        if (tid == 1023) d_rowptr[1024] = rp + v;
        __syncthreads();
        // Phase D: CSR fill
        for (int e = tid; e < NE; e += 1024) {
            int rs = d_kept_rs[e];
            if (rs < 0) continue;
            int rd = d_kept_rd[e];
            int p = d_rowptr[rs] + atomicAdd(&s_cur[rs], 1);
            d_adj_node[p] = rd; d_adj_edge[p] = e; d_adj_sign[p] = -1.f;
            p = d_rowptr[rd] + atomicAdd(&s_cur[rd], 1);
            d_adj_node[p] = rs; d_adj_edge[p] = e; d_adj_sign[p] = 1.f;
        }
    }
    zero_tickets((float4*)out, 4, ZR_RANK_1, ZR_TOPO_1);
}

// ---------------- fused block reduction of two floats (1024 threads) ---------
__device__ __forceinline__ float2 blockReduce2(float a, float b, float2* red) {
    __syncthreads();
#pragma unroll
    for (int o = 16; o; o >>= 1) {
        a += __shfl_down_sync(0xffffffffu, a, o);
        b += __shfl_down_sync(0xffffffffu, b, o);
    }
    int lane = threadIdx.x & 31, w = threadIdx.x >> 5;
    if (lane == 0) red[w] = make_float2(a, b);
    __syncthreads();
    if (w == 0) {
        float2 x = red[lane];
#pragma unroll
        for (int o = 16; o; o >>= 1) {
            x.x += __shfl_down_sync(0xffffffffu, x.x, o);
            x.y += __shfl_down_sync(0xffffffffu, x.y, o);
        }
        if (lane == 0) red[0] = x;
    }
    __syncthreads();
    return red[0];
}

// ---------------- K6: mega: block0 Lanczos; workers zero-tail + features -----
__global__ void __launch_bounds__(1024) k_mega(
    float* __restrict__ out,
    const float* __restrict__ x_n,  const float* __restrict__ x_e,
    const float* __restrict__ x_n0, const float* __restrict__ x_e0)
{
    int tid = threadIdx.x;
    if (blockIdx.x == 0) {
        // ---- Lanczos on L0 (kept-subgraph Laplacian), n = 1024 ----
        __shared__ float sv[KK];
        __shared__ float2 red[32];
        __shared__ float salpha[LANM], sbeta[LANM];
        __shared__ int   smeff;
        int r = tid;
        int p0 = d_rowptr[r], p1 = d_rowptr[r + 1];
        float degf = (float)(p1 - p0);
        unsigned h = (unsigned)r * 2654435761u + 0x9e3779b9u;
        h ^= h >> 16; h *= 0x85ebca6bu; h ^= h >> 13;
        float vr = ((float)(h & 0xFFFFFFu) / 16777216.0f) - 0.5f;
        float2 nn0 = blockReduce2(vr * vr, 0.f, red);
        vr = vr * rsqrtf(nn0.x);
        sv[r] = vr;
        if (r == 0) smeff = LANM;
        float vprev = 0.f, beta = 0.f;
        __syncthreads();
        for (int j = 0; j < LANM; j++) {
            float vcur = sv[r];
            float w = degf * vcur;
            for (int k = p0; k < p1; k++) w -= sv[d_adj_node[k]];
            w -= beta * vprev;
            float2 ab = blockReduce2(w * vcur, w * w, red);
            float alpha = ab.x;
            float b2 = ab.y - alpha * alpha;
            float nb = (b2 > 0.f) ? sqrtf(b2) : 0.f;
            if (r == 0) { salpha[j] = alpha; sbeta[j] = nb; }
            if (nb < 1e-10f) { if (r == 0) smeff = j + 1; break; }
            vprev = vcur;
            sv[r] = (w - alpha * vcur) / nb;
            beta = nb;
            __syncthreads();
        }
        __syncthreads();
        int meff = smeff;
        // warp-parallel 32-way multisection Sturm bisection on T
        if (r < 32) {
            float lo = 1e30f, hi = -1e30f;
            for (int i = 0; i < meff; i++) {
                float a  = salpha[i];
                float bl = (i > 0) ? fabsf(sbeta[i - 1]) : 0.f;
                float br = (i < meff - 1) ? fabsf(sbeta[i]) : 0.f;
                lo = fminf(lo, a - bl - br);
                hi = fmaxf(hi, a + bl + br);
            }
            if (!(hi > lo)) hi = lo + 1.f;
            for (int round = 0; round < 10; round++) {
                float x = lo + (hi - lo) * ((float)(r + 1) / 33.0f);
                int cnt = 0; float dd = 1.f;
                for (int i = 0; i < meff; i++) {
                    float bb = (i > 0) ? sbeta[i - 1] * sbeta[i - 1] : 0.f;
                    dd = salpha[i] - x - bb / dd;
                    if (dd < 0.f) cnt++;
                    if (dd == 0.f) dd = -1e-20f;
                }
                bool allbelow = (cnt >= meff);
                unsigned mhi = __ballot_sync(0xffffffffu, allbelow);
                float nlo = lo, nhi = hi;
                if (mhi) {
                    int first = __ffs(mhi) - 1;
                    nhi = lo + (hi - lo) * ((float)(first + 1) / 33.0f);
                }
                unsigned mlo = ~mhi;
                if (mlo) {
                    int last = 31 - __clz(mlo);
                    nlo = lo + (hi - lo) * ((float)(last + 1) / 33.0f);
                }
                lo = nlo; hi = nhi;
            }
            if (r == 0) {
                float lam = 0.5f * (lo + hi);
                if (!(lam > 0.f)) lam = 1.f;
                d_scale = 2.0f / lam;
            }
        }
    } else {
        // ---- workers: zero tail via tickets, then feature outputs ----
        float4* o4 = (float4*)out;
        zero_tickets(o4, 5, ZR_TOPO_1, ZR_MEGA_1);

        const float4* xn4  = (const float4*)x_n;
        const float4* xe4  = (const float4*)x_e;
        const float4* xn04 = (const float4*)x_n0;
        const float4* xe04 = (const float4*)x_e0;
        unsigned stride = (gridDim.x - 1) * 1024u;
        unsigned t0 = (blockIdx.x - 1) * 1024u + tid;
        for (unsigned i = t0; i < 65536u; i += stride) {      // kept-node feats
            unsigned rr = i >> 6, c = i & 63;
            int n = d_idx_keep[rr];
            float s = d_score_n[n];
            float4 a = xn4[(size_t)n * 64 + c];
            a.x *= s; a.y *= s; a.z *= s; a.w *= s;
            o4[OFF_XN / 4 + i]  = a;
            o4[OFF_XN0 / 4 + i] = xn04[(size_t)n * 64 + c];
        }
        for (unsigned i = t0; i < 524288u; i += stride) {     // edge feats
            unsigned e = i >> 6, c = i & 63;
            float kf = d_keep_f[e];
            float s = d_score_e[e] * kf;
            float4 a = xe4[(size_t)e * 64 + c];
            a.x *= s; a.y *= s; a.z *= s; a.w *= s;
            o4[OFF_XE / 4 + i] = a;
            float4 b0 = xe04[(size_t)e * 64 + c];
            b0.x *= kf; b0.y *= kf; b0.z *= kf; b0.w *= kf;
            o4[OFF_XE0 / 4 + i] = b0;
        }
    }
}

// ---------------- K7: scaled sparse fills + ticket reset ----------------------
// Blocks 0..127: L1s pair-scatter, FOUR warps per kept-node row (latency fix);
// direct L0 diagonal. Blocks 128..135: PAR stores + L0 off-diag atomics.
__global__ void __launch_bounds__(1024) k_sparse(float* __restrict__ out) {
    float s = d_scale;
    int bid = blockIdx.x, tid = threadIdx.x;
    if (bid < 128) {
        int gw = bid * 32 + (tid >> 5);       // 4096 warps
        int r = gw >> 2;                      // kept-node row, 0..1023
        int q = gw & 3;                       // quarter
        int lane = tid & 31;
        int p0 = d_rowptr[r], p1 = d_rowptr[r + 1];
        int deg = p1 - p0;
        if (q == 0 && lane == 0)              // L0 diagonal, direct store
            out[OFF_L0 + (size_t)r * KK + r] = (float)deg * s;
        float* L1 = out + OFF_L1;
        int tot = deg * deg;
        for (int p = (q << 5) + lane; p < tot; p += 128) {
            int i = p0 + p / deg;
            int j = p0 + p % deg;
            atomicAdd(&L1[(size_t)d_adj_edge[i] * NE + d_adj_edge[j]],
                      s * d_adj_sign[i] * d_adj_sign[j]);
        }
    } else {
        if (bid == 128 && tid < 6) d_tick[tid] = 0u;   // reset for next replay
        int e = (bid - 128) * 1024 + tid;
        if (e < NE) {
            int rs = d_kept_rs[e];
            if (rs >= 0) {
                int rd = d_kept_rd[e];
                out[OFF_PAR + (size_t)rs * NE + e] = -1.f;
                out[OFF_PAR + (size_t)rd * NE + e] =  1.f;
                float* L0 = out + OFF_L0;
                atomicAdd(&L0[(size_t)rs * KK + rd], -s);
                atomicAdd(&L0[(size_t)rd * KK + rs], -s);
            }
        }
    }
}

// ---------------- launch ------------------------------------------------------
extern "C" void kernel_launch(void* const* d_in, const int* in_sizes, int n_in,
                              void* d_out, int out_size) {
    const float* x_n  = (const float*)d_in[0];
    const int*   ein  = (const int*)d_in[1];
    const float* ewn  = (const float*)d_in[2];
    const float* x_e  = (const float*)d_in[3];
    const int*   eie  = (const int*)d_in[4];
    const float* ewe  = (const float*)d_in[5];
    const int*   ei   = (const int*)d_in[6];
    // d_in[7] n_batch, d_in[8] e_batch: unused (single graph)
    const float* x_n0 = (const float*)d_in[9];
    const float* x_e0 = (const float*)d_in[10];
    const float* Wn0  = (const float*)d_in[11];
    const float* Wn1  = (const float*)d_in[12];
    const float* bn   = (const float*)d_in[13];
    const float* We0  = (const float*)d_in[14];
    const float* We1  = (const float*)d_in[15];
    const float* be   = (const float*)d_in[16];
    float* out = (float*)d_out;

    k_rows<<<ZGRID, 1024>>>(out, x_n, x_e, Wn0, Wn1, We0, We1);
    k_scatter_g<<<ZGRID, 1024>>>(out, ein, ewn, eie, ewe);
    k_scores_joint<<<ZGRID, 1024>>>(out, bn, be, ei);
    k_rank<<<ZGRID, 1024>>>(out);
    k_topo<<<ZGRID, 1024>>>(out, ei);
    k_mega<<<ZGRID, 1024>>>(out, x_n, x_e, x_n0, x_e0);
    k_sparse<<<136, 1024>>>(out);
}

// round 9
// speedup vs baseline: 1.4205x; 1.4205x over previous
#include <cuda_runtime.h>
#include <math.h>

// Problem constants (static shapes from reference)
#define NN   2048      // nodes
#define NE   8192      // edges (E)
#define KK   1024      // K_KEEP
#define MNE  16384     // node-graph edges
#define MEE  65536     // edge-graph edges
#define CC   256       // feature dim (CN == CE)
#define LANM 48        // Lanczos iterations (R5 numerics, rel_err ~7e-5)

// Output layout (float offsets, concatenated flattened outputs in tuple order)
#define OFF_XN   0u         // x_n_out   [1024,256]
#define OFF_L0   262144u    // L0s       [1024,1024]
#define OFF_XE   1310720u   // x_e_out   [8192,256]
#define OFF_L1   3407872u   // L1s       [8192,8192]
#define OFF_PAR  70516736u  // par_masked[1024,8192]
#define OFF_XN0  78905344u  // x_n0_out  [1024,256]
#define OFF_XE0  79167488u  // x_e0_out  [8192,256]

// ---- static distributed zero plan (NO atomics) ------------------------------
// Flat zero space in float4: [0, 18874368) -> L1s+PAR contiguous,
// [18874368, 19136512) -> L0.
#define ZTOT     19136512u
#define ZB_SPLIT 18874368u
// per-kernel flat ranges [z0, z1)
#define Z_K1_0   0u
#define Z_K1_1   3276800u
#define Z_K2_1   6553600u
#define Z_K3_1   9830400u
#define Z_K4_1   13107200u
#define Z_K5_1   16384000u
#define Z_K6_1   ZTOT

#define ZGRID 592

// ---------------- scratch (device globals; re-initialized every launch) -----
__device__ float d_t_n[NN], d_u_n[NN], d_t_e[NE], d_u_e[NE];
__device__ float d_g_n[NN], d_g_e[NE];
__device__ float d_score_n[NN], d_score_e[NE], d_joint[NN];
__device__ int   d_mask[NN], d_idx_keep[KK];
__device__ float d_keep_f[NE];
__device__ int   d_kept_rs[NE], d_kept_rd[NE];
__device__ int   d_rowptr[KK + 1];
__device__ int   d_adj_node[2 * NE], d_adj_edge[2 * NE];
__device__ float d_adj_sign[2 * NE];
__device__ float d_scale;        // 2 / lambda_max(L0)

// ---------------- static zero slice (proven grid-stride float4 pattern) -----
__device__ __forceinline__ void zero_slice(float4* o4, int zb, int nzb,
                                           unsigned z0, unsigned z1) {
    const float4 z4 = make_float4(0.f, 0.f, 0.f, 0.f);
    for (unsigned i = z0 + (unsigned)zb * 1024u + threadIdx.x; i < z1;
         i += (unsigned)nzb * 1024u) {
        unsigned a = (i < ZB_SPLIT) ? (OFF_L1 / 4u + i)
                                    : (OFF_L0 / 4u + (i - ZB_SPLIT));
        o4[a] = z4;
    }
}

// ---------------- K1: row projections (+ scratch zero) + zero slice ---------
#define NC1 80
__global__ void __launch_bounds__(1024) k_rows(
    float* __restrict__ out,
    const float* __restrict__ x_n, const float* __restrict__ x_e,
    const float* __restrict__ Wn0, const float* __restrict__ Wn1,
    const float* __restrict__ We0, const float* __restrict__ We1) {
    int bid = blockIdx.x, tid = threadIdx.x;
    if (bid < NC1) {
        int gt = bid * 1024 + tid;
        if (gt < NN + NE) {                 // zero per-launch accumulators
            if (gt < NN) { d_g_n[gt] = 0.f; d_joint[gt] = 0.f; }
            else d_g_e[gt - NN] = 0.f;
        }
        int w = bid * 32 + (tid >> 5);      // 2560 warps, 4 rows each
        int lane = tid & 31;
#pragma unroll
        for (int i = 0; i < 4; i++) {
            int row = w + i * 2560;
            const float *x, *W0, *W1;
            if (row < NN) { x = x_n + (size_t)row * CC;        W0 = Wn0; W1 = Wn1; }
            else          { x = x_e + (size_t)(row - NN) * CC; W0 = We0; W1 = We1; }
            float u = 0.f, t = 0.f;
#pragma unroll
            for (int k = lane; k < CC; k += 32) {
                float xv = x[k];
                float w1 = W1[k];
                t = fmaf(xv, w1, t);
                u = fmaf(xv, W0[k] + w1, u);
            }
#pragma unroll
            for (int o = 16; o; o >>= 1) {
                u += __shfl_down_sync(0xffffffffu, u, o);
                t += __shfl_down_sync(0xffffffffu, t, o);
            }
            if (lane == 0) {
                if (row < NN) { d_u_n[row] = u; d_t_n[row] = t; }
                else          { d_u_e[row - NN] = u; d_t_e[row - NN] = t; }
            }
        }
    } else {
        zero_slice((float4*)out, bid - NC1, ZGRID - NC1, Z_K1_0, Z_K1_1);
    }
}

// ---------------- K2: scatter weighted scalar aggregates + zero slice -------
#define NC2 80
__global__ void __launch_bounds__(1024) k_scatter_g(
    float* __restrict__ out,
    const int* __restrict__ ein, const float* __restrict__ ewn,
    const int* __restrict__ eie, const float* __restrict__ ewe) {
    int bid = blockIdx.x, tid = threadIdx.x;
    if (bid < NC2) {
        int i = bid * 1024 + tid;           // exactly MNE+MEE = 81920
        if (i < MNE) {
            int s = ein[i], d = ein[MNE + i];
            atomicAdd(&d_g_n[d], ewn[i] * d_t_n[s]);
        } else {
            int j = i - MNE;
            int s = eie[j], d = eie[MEE + j];
            atomicAdd(&d_g_e[d], ewe[j] * d_t_e[s]);
        }
    } else {
        zero_slice((float4*)out, bid - NC2, ZGRID - NC2, Z_K1_1, Z_K2_1);
    }
}

// ---------------- K3: sigmoid scores + joint accumulation + zero slice ------
#define NC3 10
__global__ void __launch_bounds__(1024) k_scores_joint(
    float* __restrict__ out,
    const float* __restrict__ bn, const float* __restrict__ be,
    const int* __restrict__ ei) {
    int bid = blockIdx.x, tid = threadIdx.x;
    if (bid < NC3) {
        int i = bid * 1024 + tid;           // exactly NN+NE = 10240
        if (i < NN) {
            float z = d_u_n[i] - d_g_n[i] + bn[0];
            float s = 1.f / (1.f + expf(-z));
            d_score_n[i] = s;
            atomicAdd(&d_joint[i], s);
        } else {
            int j = i - NN;
            float z = d_u_e[j] - d_g_e[j] + be[0];
            float s = 1.f / (1.f + expf(-z));
            d_score_e[j] = s;
            float c = 0.125f * s;
            atomicAdd(&d_joint[ei[j]], c);
            atomicAdd(&d_joint[ei[NE + j]], c);
        }
    } else {
        zero_slice((float4*)out, bid - NC3, ZGRID - NC3, Z_K2_1, Z_K3_1);
    }
}

// ---------------- K4: exact top-K rank counting + zero slice ----------------
#define NC4 64
__global__ void __launch_bounds__(1024) k_rank(float* __restrict__ out) {
    int bid = blockIdx.x, tid = threadIdx.x;
    if (bid < NC4) {
        int w = bid * 32 + (tid >> 5);      // 2048 warps, one node each
        int lane = tid & 31;
        float vi = d_joint[w];
        int cnt = 0;
        for (int j = lane; j < NN; j += 32) {
            float vj = d_joint[j];
            cnt += (vj > vi) || (vj == vi && j < w);
        }
#pragma unroll
        for (int o = 16; o; o >>= 1) cnt += __shfl_down_sync(0xffffffffu, cnt, o);
        if (lane == 0) d_mask[w] = (cnt < KK) ? 1 : 0;
    } else {
        zero_slice((float4*)out, bid - NC4, ZGRID - NC4, Z_K3_1, Z_K4_1);
    }
}

// ---------------- block exclusive scan helper (1024 threads) ----------------
__device__ __forceinline__ int exclScan1024(int v, int* tmp) {
    int lane = threadIdx.x & 31, w = threadIdx.x >> 5;
    int incl = v;
#pragma unroll
    for (int o = 1; o < 32; o <<= 1) {
        int n = __shfl_up_sync(0xffffffffu, incl, o);
        if (lane >= o) incl += n;
    }
    if (lane == 31) tmp[w] = incl;
    __syncthreads();
    if (w == 0) {
        int x = tmp[lane];
#pragma unroll
        for (int o = 1; o < 32; o <<= 1) {
            int n = __shfl_up_sync(0xffffffffu, x, o);
            if (lane >= o) x += n;
        }
        tmp[lane] = x;
    }
    __syncthreads();
    int off = w ? tmp[w - 1] : 0;
    return off + incl - v;
}

// ---------------- K5: topology (block 0) + zero slice ------------------------
__global__ void __launch_bounds__(1024) k_topo(float* __restrict__ out,
                                               const int* __restrict__ ei) {
    int tid = threadIdx.x;
    if (blockIdx.x == 0) {
        __shared__ int s_row[NN];
        __shared__ int s_deg[KK];
        __shared__ int s_cur[KK];
        __shared__ int tmp[32];
        // Phase A: compact kept nodes -> idx_keep (ascending), row map
        int m0 = d_mask[2 * tid], m1 = d_mask[2 * tid + 1];
        int ex = exclScan1024(m0 + m1, tmp);
        if (m0) { s_row[2 * tid] = ex; d_idx_keep[ex] = 2 * tid; }
        else    s_row[2 * tid] = -1;
        int ex1 = ex + m0;
        if (m1) { s_row[2 * tid + 1] = ex1; d_idx_keep[ex1] = 2 * tid + 1; }
        else    s_row[2 * tid + 1] = -1;
        s_deg[tid] = 0;
        s_cur[tid] = 0;
        __syncthreads();
        // Phase B: keep_e + endpoint rows + degree count
        for (int e = tid; e < NE; e += 1024) {
            int s = ei[e], d = ei[NE + e];
            int rs = s_row[s], rd = s_row[d];
            int keep = (rs >= 0) && (rd >= 0);
            d_keep_f[e] = keep ? 1.f : 0.f;
            if (keep && s != d) {
                d_kept_rs[e] = rs;
                d_kept_rd[e] = rd;
                atomicAdd(&s_deg[rs], 1);
                atomicAdd(&s_deg[rd], 1);
            } else {
                d_kept_rs[e] = -1;
            }
        }
        __syncthreads();
        // Phase C: row pointers
        int v = s_deg[tid];
        int rp = exclScan1024(v, tmp);
        d_rowptr[tid] = rp;
        if (tid == 1023) d_rowptr[1024] = rp + v;
        __syncthreads();
        // Phase D: CSR fill
        for (int e = tid; e < NE; e += 1024) {
            int rs = d_kept_rs[e];
            if (rs < 0) continue;
            int rd = d_kept_rd[e];
            int p = d_rowptr[rs] + atomicAdd(&s_cur[rs], 1);
            d_adj_node[p] = rd; d_adj_edge[p] = e; d_adj_sign[p] = -1.f;
            p = d_rowptr[rd] + atomicAdd(&s_cur[rd], 1);
            d_adj_node[p] = rs; d_adj_edge[p] = e; d_adj_sign[p] = 1.f;
        }
    } else {
        zero_slice((float4*)out, blockIdx.x - 1, ZGRID - 1, Z_K4_1, Z_K5_1);
    }
}

// ---------------- fused block reduction of two floats (1024 threads) ---------
__device__ __forceinline__ float2 blockReduce2(float a, float b, float2* red) {
    __syncthreads();
#pragma unroll
    for (int o = 16; o; o >>= 1) {
        a += __shfl_down_sync(0xffffffffu, a, o);
        b += __shfl_down_sync(0xffffffffu, b, o);
    }
    int lane = threadIdx.x & 31, w = threadIdx.x >> 5;
    if (lane == 0) red[w] = make_float2(a, b);
    __syncthreads();
    if (w == 0) {
        float2 x = red[lane];
#pragma unroll
        for (int o = 16; o; o >>= 1) {
            x.x += __shfl_down_sync(0xffffffffu, x.x, o);
            x.y += __shfl_down_sync(0xffffffffu, x.y, o);
        }
        if (lane == 0) red[0] = x;
    }
    __syncthreads();
    return red[0];
}

// ---------------- K6: mega: block0 Lanczos; workers zero tail + features -----
__global__ void __launch_bounds__(1024) k_mega(
    float* __restrict__ out,
    const float* __restrict__ x_n,  const float* __restrict__ x_e,
    const float* __restrict__ x_n0, const float* __restrict__ x_e0)
{
    int tid = threadIdx.x;
    if (blockIdx.x == 0) {
        // ---- Lanczos on L0 (kept-subgraph Laplacian), n = 1024 ----
        __shared__ float sv[KK];
        __shared__ float2 red[32];
        __shared__ float salpha[LANM], sbeta[LANM];
        __shared__ int   smeff;
        int r = tid;
        int p0 = d_rowptr[r], p1 = d_rowptr[r + 1];
        float degf = (float)(p1 - p0);
        unsigned h = (unsigned)r * 2654435761u + 0x9e3779b9u;
        h ^= h >> 16; h *= 0x85ebca6bu; h ^= h >> 13;
        float vr = ((float)(h & 0xFFFFFFu) / 16777216.0f) - 0.5f;
        float2 nn0 = blockReduce2(vr * vr, 0.f, red);
        vr = vr * rsqrtf(nn0.x);
        sv[r] = vr;
        if (r == 0) smeff = LANM;
        float vprev = 0.f, beta = 0.f;
        __syncthreads();
        for (int j = 0; j < LANM; j++) {
            float vcur = sv[r];
            float w = degf * vcur;
            for (int k = p0; k < p1; k++) w -= sv[d_adj_node[k]];
            w -= beta * vprev;
            float2 ab = blockReduce2(w * vcur, w * w, red);
            float alpha = ab.x;
            float b2 = ab.y - alpha * alpha;
            float nb = (b2 > 0.f) ? sqrtf(b2) : 0.f;
            if (r == 0) { salpha[j] = alpha; sbeta[j] = nb; }
            if (nb < 1e-10f) { if (r == 0) smeff = j + 1; break; }
            vprev = vcur;
            sv[r] = (w - alpha * vcur) / nb;
            beta = nb;
            __syncthreads();
        }
        __syncthreads();
        int meff = smeff;
        // warp-parallel 32-way multisection Sturm bisection on T
        if (r < 32) {
            float lo = 1e30f, hi = -1e30f;
            for (int i = 0; i < meff; i++) {
                float a  = salpha[i];
                float bl = (i > 0) ? fabsf(sbeta[i - 1]) : 0.f;
                float br = (i < meff - 1) ? fabsf(sbeta[i]) : 0.f;
                lo = fminf(lo, a - bl - br);
                hi = fmaxf(hi, a + bl + br);
            }
            if (!(hi > lo)) hi = lo + 1.f;
            for (int round = 0; round < 10; round++) {
                float x = lo + (hi - lo) * ((float)(r + 1) / 33.0f);
                int cnt = 0; float dd = 1.f;
                for (int i = 0; i < meff; i++) {
                    float bb = (i > 0) ? sbeta[i - 1] * sbeta[i - 1] : 0.f;
                    dd = salpha[i] - x - bb / dd;
                    if (dd < 0.f) cnt++;
                    if (dd == 0.f) dd = -1e-20f;
                }
                bool allbelow = (cnt >= meff);
                unsigned mhi = __ballot_sync(0xffffffffu, allbelow);
                float nlo = lo, nhi = hi;
                if (mhi) {
                    int first = __ffs(mhi) - 1;
                    nhi = lo + (hi - lo) * ((float)(first + 1) / 33.0f);
                }
                unsigned mlo = ~mhi;
                if (mlo) {
                    int last = 31 - __clz(mlo);
                    nlo = lo + (hi - lo) * ((float)(last + 1) / 33.0f);
                }
                lo = nlo; hi = nhi;
            }
            if (r == 0) {
                float lam = 0.5f * (lo + hi);
                if (!(lam > 0.f)) lam = 1.f;
                d_scale = 2.0f / lam;
            }
        }
    } else {
        // ---- workers: zero tail slice, then feature outputs ----
        float4* o4 = (float4*)out;
        zero_slice(o4, blockIdx.x - 1, ZGRID - 1, Z_K5_1, Z_K6_1);

        const float4* xn4  = (const float4*)x_n;
        const float4* xe4  = (const float4*)x_e;
        const float4* xn04 = (const float4*)x_n0;
        const float4* xe04 = (const float4*)x_e0;
        unsigned stride = (ZGRID - 1) * 1024u;
        unsigned t0 = (blockIdx.x - 1) * 1024u + tid;
        for (unsigned i = t0; i < 65536u; i += stride) {      // kept-node feats
            unsigned rr = i >> 6, c = i & 63;
            int n = d_idx_keep[rr];
            float s = d_score_n[n];
            float4 a = xn4[(size_t)n * 64 + c];
            a.x *= s; a.y *= s; a.z *= s; a.w *= s;
            o4[OFF_XN / 4 + i]  = a;
            o4[OFF_XN0 / 4 + i] = xn04[(size_t)n * 64 + c];
        }
        for (unsigned i = t0; i < 524288u; i += stride) {     // edge feats
            unsigned e = i >> 6, c = i & 63;
            float kf = d_keep_f[e];
            float s = d_score_e[e] * kf;
            float4 a = xe4[(size_t)e * 64 + c];
            a.x *= s; a.y *= s; a.z *= s; a.w *= s;
            o4[OFF_XE / 4 + i] = a;
            float4 b0 = xe04[(size_t)e * 64 + c];
            b0.x *= kf; b0.y *= kf; b0.z *= kf; b0.w *= kf;
            o4[OFF_XE0 / 4 + i] = b0;
        }
    }
}

// ---------------- K7: scaled sparse fills -------------------------------------
// Blocks 0..127: L1s pair-scatter, four warps per kept-node row; direct L0 diag.
// Blocks 128..135: PAR stores + L0 off-diagonal atomics per kept edge.
__global__ void __launch_bounds__(1024) k_sparse(float* __restrict__ out) {
    float s = d_scale;
    int bid = blockIdx.x, tid = threadIdx.x;
    if (bid < 128) {
        int gw = bid * 32 + (tid >> 5);       // 4096 warps
        int r = gw >> 2;                      // kept-node row, 0..1023
        int q = gw & 3;                       // quarter
        int lane = tid & 31;
        int p0 = d_rowptr[r], p1 = d_rowptr[r + 1];
        int deg = p1 - p0;
        if (q == 0 && lane == 0)              // L0 diagonal, direct store
            out[OFF_L0 + (size_t)r * KK + r] = (float)deg * s;
        float* L1 = out + OFF_L1;
        int tot = deg * deg;
        for (int p = (q << 5) + lane; p < tot; p += 128) {
            int i = p0 + p / deg;
            int j = p0 + p % deg;
            atomicAdd(&L1[(size_t)d_adj_edge[i] * NE + d_adj_edge[j]],
                      s * d_adj_sign[i] * d_adj_sign[j]);
        }
    } else {
        int e = (bid - 128) * 1024 + tid;
        if (e < NE) {
            int rs = d_kept_rs[e];
            if (rs >= 0) {
                int rd = d_kept_rd[e];
                out[OFF_PAR + (size_t)rs * NE + e] = -1.f;
                out[OFF_PAR + (size_t)rd * NE + e] =  1.f;
                float* L0 = out + OFF_L0;
                atomicAdd(&L0[(size_t)rs * KK + rd], -s);
                atomicAdd(&L0[(size_t)rd * KK + rs], -s);
            }
        }
    }
}

// ---------------- launch ------------------------------------------------------
extern "C" void kernel_launch(void* const* d_in, const int* in_sizes, int n_in,
                              void* d_out, int out_size) {
    const float* x_n  = (const float*)d_in[0];
    const int*   ein  = (const int*)d_in[1];
    const float* ewn  = (const float*)d_in[2];
    const float* x_e  = (const float*)d_in[3];
    const int*   eie  = (const int*)d_in[4];
    const float* ewe  = (const float*)d_in[5];
    const int*   ei   = (const int*)d_in[6];
    // d_in[7] n_batch, d_in[8] e_batch: unused (single graph)
    const float* x_n0 = (const float*)d_in[9];
    const float* x_e0 = (const float*)d_in[10];
    const float* Wn0  = (const float*)d_in[11];
    const float* Wn1  = (const float*)d_in[12];
    const float* bn   = (const float*)d_in[13];
    const float* We0  = (const float*)d_in[14];
    const float* We1  = (const float*)d_in[15];
    const float* be   = (const float*)d_in[16];
    float* out = (float*)d_out;

    k_rows<<<ZGRID, 1024>>>(out, x_n, x_e, Wn0, Wn1, We0, We1);
    k_scatter_g<<<ZGRID, 1024>>>(out, ein, ewn, eie, ewe);
    k_scores_joint<<<ZGRID, 1024>>>(out, bn, be, ei);
    k_rank<<<ZGRID, 1024>>>(out);
    k_topo<<<ZGRID, 1024>>>(out, ei);
    k_mega<<<ZGRID, 1024>>>(out, x_n, x_e, x_n0, x_e0);
    k_sparse<<<136, 1024>>>(out);
}